// round 15
// baseline (speedup 1.0000x reference)
#include <cuda_runtime.h>
#include <cuda_bf16.h>
#include <cstdint>
#include <cstddef>

#define DIM 1024
#define HID 512
#define NEXP 16
#define TOPK 4
#define MAXT 2048
#define NEXP1 17

// ======================= device scratch (no allocs allowed) =======================
__device__ __nv_bfloat16 g_xh[MAXT * DIM], g_xl[MAXT * DIM];
__device__ __nv_bfloat16 g_w1h[NEXP * HID * DIM], g_w1l[NEXP * HID * DIM];
__device__ __nv_bfloat16 g_w3h[NEXP * HID * DIM], g_w3l[NEXP * HID * DIM];
__device__ __nv_bfloat16 g_w2h[NEXP * DIM * HID], g_w2l[NEXP * DIM * HID];
__device__ __nv_bfloat16 g_sw1h[HID * DIM], g_sw1l[HID * DIM];
__device__ __nv_bfloat16 g_sw3h[HID * DIM], g_sw3l[HID * DIM];
__device__ __nv_bfloat16 g_sw2h[DIM * HID], g_sw2l[DIM * HID];
__device__ __nv_bfloat16 g_acth[NEXP1 * MAXT * HID], g_actl[NEXP1 * MAXT * HID];
__device__ int   g_counts[NEXP1];
__device__ int   g_pair_token[NEXP1 * MAXT];
__device__ float g_pair_weight[NEXP1 * MAXT];

// ======================= helpers =======================
__device__ __forceinline__ uint32_t smem_u32(const void* p) {
    uint32_t a;
    asm("{ .reg .u64 t; cvta.to.shared.u64 t, %1; cvt.u32.u64 %0, t; }" : "=r"(a) : "l"(p));
    return a;
}
__device__ __forceinline__ void cp16(uint32_t s, const void* g) {
    asm volatile("cp.async.cg.shared.global [%0], [%1], 16;" :: "r"(s), "l"(g));
}
#define CP_COMMIT() asm volatile("cp.async.commit_group;" ::: "memory")
#define CP_WAIT1()  asm volatile("cp.async.wait_group 1;" ::: "memory")
#define CP_WAIT0()  asm volatile("cp.async.wait_group 0;" ::: "memory")

__device__ __forceinline__ void ldsm4(uint32_t* r, uint32_t addr) {
    asm volatile("ldmatrix.sync.aligned.m8n8.x4.shared.b16 {%0,%1,%2,%3}, [%4];"
                 : "=r"(r[0]), "=r"(r[1]), "=r"(r[2]), "=r"(r[3]) : "r"(addr));
}
__device__ __forceinline__ void mma16816(float* c, const uint32_t* a, const uint32_t* b) {
    asm volatile(
        "mma.sync.aligned.m16n8k16.row.col.f32.bf16.bf16.f32 "
        "{%0,%1,%2,%3}, {%4,%5,%6,%7}, {%8,%9}, {%0,%1,%2,%3};"
        : "+f"(c[0]), "+f"(c[1]), "+f"(c[2]), "+f"(c[3])
        : "r"(a[0]), "r"(a[1]), "r"(a[2]), "r"(a[3]), "r"(b[0]), "r"(b[1]));
}

// BK=64: 64 bf16 = 128B data + 16B pad = 144B pitch (conflict-free ldmatrix)
#define PITCH 144
#define AT_BYTES  (128 * PITCH)   // 18432
#define BT_BYTES  (64 * PITCH)    //  9216
// gemm1 stage: Ah Al | B1h B3h B1l B3l  = 73728
#define G1_AH 0
#define G1_AL AT_BYTES
#define G1_B1H (2 * AT_BYTES)
#define G1_B3H (2 * AT_BYTES + BT_BYTES)
#define G1_B1L (2 * AT_BYTES + 2 * BT_BYTES)
#define G1_B3L (2 * AT_BYTES + 3 * BT_BYTES)
// gemm2 stage: Ah Al Bh Bl (all 128-row) = 73728
#define G2_AH 0
#define G2_AL AT_BYTES
#define G2_BH (2 * AT_BYTES)
#define G2_BL (3 * AT_BYTES)
#define STAGE 73728
#define NSTAGE 3
#define SMEM_DYN (NSTAGE * STAGE)   // 221184

// ======================= fused fp32 -> bf16 hi/lo split (ONE launch) =======================
__device__ __forceinline__ void split4(const float* __restrict__ src, int i,
                                       __nv_bfloat16* hi, __nv_bfloat16* lo) {
    float4 v = *(const float4*)(src + i);
    __nv_bfloat16 h0 = __float2bfloat16(v.x), h1 = __float2bfloat16(v.y);
    __nv_bfloat16 h2 = __float2bfloat16(v.z), h3 = __float2bfloat16(v.w);
    __nv_bfloat162 H0; H0.x = h0; H0.y = h1;
    __nv_bfloat162 H1; H1.x = h2; H1.y = h3;
    *(__nv_bfloat162*)(hi + i)     = H0;
    *(__nv_bfloat162*)(hi + i + 2) = H1;
    __nv_bfloat162 L0, L1;
    L0.x = __float2bfloat16(v.x - __bfloat162float(h0));
    L0.y = __float2bfloat16(v.y - __bfloat162float(h1));
    L1.x = __float2bfloat16(v.z - __bfloat162float(h2));
    L1.y = __float2bfloat16(v.w - __bfloat162float(h3));
    *(__nv_bfloat162*)(lo + i)     = L0;
    *(__nv_bfloat162*)(lo + i + 2) = L1;
}

__global__ void split_all(const float* __restrict__ x,
                          const float* __restrict__ w1, const float* __restrict__ w3,
                          const float* __restrict__ w2,
                          const float* __restrict__ sw1, const float* __restrict__ sw3,
                          const float* __restrict__ sw2) {
    const int NX = MAXT * DIM;
    const int NW = NEXP * HID * DIM;
    const int NS = HID * DIM;
    int i = (blockIdx.x * blockDim.x + threadIdx.x) * 4;
    if (i < NX) { split4(x,   i, g_xh,  g_xl);  return; }
    i -= NX;
    if (i < NW) { split4(w1,  i, g_w1h, g_w1l); return; }
    i -= NW;
    if (i < NW) { split4(w3,  i, g_w3h, g_w3l); return; }
    i -= NW;
    if (i < NW) { split4(w2,  i, g_w2h, g_w2l); return; }
    i -= NW;
    if (i < NS) { split4(sw1, i, g_sw1h, g_sw1l); return; }
    i -= NS;
    if (i < NS) { split4(sw3, i, g_sw3h, g_sw3l); return; }
    i -= NS;
    if (i < NS) { split4(sw2, i, g_sw2h, g_sw2l); }
}

// ======================= init: zero output + reset counters =======================
__global__ void init_kernel(float* __restrict__ out, int out_n, int T) {
    int i = (blockIdx.x * blockDim.x + threadIdx.x) * 4;
    if (i < out_n) *(float4*)(out + i) = make_float4(0.f, 0.f, 0.f, 0.f);
    if (blockIdx.x == 0) {
        int t = threadIdx.x;
        if (t < NEXP) g_counts[t] = 0;
        else if (t == NEXP) g_counts[NEXP] = T;
    }
}

// ======================= router =======================
__global__ void router_kernel(const float* __restrict__ x,
                              const float* __restrict__ gw, int T) {
    int t = blockIdx.x;
    __shared__ float xs[DIM];
    __shared__ float logits[NEXP];
    const float* xr = x + (size_t)t * DIM;
    for (int k = threadIdx.x; k < DIM; k += blockDim.x) xs[k] = xr[k];
    __syncthreads();

    int e = threadIdx.x >> 4;
    int l = threadIdx.x & 15;
    const float* w = gw + (size_t)e * DIM;
    float s = 0.f;
    for (int k = l; k < DIM; k += 16) s += xs[k] * w[k];
    for (int off = 8; off; off >>= 1) s += __shfl_down_sync(0xffffffffu, s, off, 16);
    if (l == 0) logits[e] = s;
    __syncthreads();

    if (threadIdx.x == 0) {
        float lv[NEXP];
        #pragma unroll
        for (int i = 0; i < NEXP; i++) lv[i] = logits[i];
        int   idx[TOPK];
        float val[TOPK];
        #pragma unroll
        for (int k = 0; k < TOPK; k++) {
            int bi = 0; float bv = -1e30f;
            #pragma unroll
            for (int i = 0; i < NEXP; i++) if (lv[i] > bv) { bv = lv[i]; bi = i; }
            idx[k] = bi; val[k] = bv; lv[bi] = -1e30f;
        }
        float m = val[0];
        float wv[TOPK], sum = 0.f;
        #pragma unroll
        for (int k = 0; k < TOPK; k++) { wv[k] = __expf(val[k] - m); sum += wv[k]; }
        float inv = 1.f / sum;
        #pragma unroll
        for (int k = 0; k < TOPK; k++) {
            int ee = idx[k];
            int slot = atomicAdd(&g_counts[ee], 1);
            g_pair_token[ee * MAXT + slot]  = t;
            g_pair_weight[ee * MAXT + slot] = wv[k] * inv;
        }
        g_pair_token[NEXP * MAXT + t]  = t;
        g_pair_weight[NEXP * MAXT + t] = 1.f;
    }
}

// ======================= GEMM1: act = silu(x@W1^T)*(x@W3^T) =======================
// CTA 128 tokens x 64 hid cols, BK=64, 3-stage cp.async, 1 barrier/chunk,
// hi+lo co-resident, register-fragment double buffering across ks-steps.
__global__ __launch_bounds__(256, 1) void gemm1_mma() {
    int e   = blockIdx.z;
    int cnt = g_counts[e];
    int m0  = blockIdx.x * 128;
    if (m0 >= cnt) return;
    int n0  = blockIdx.y * 64;

    extern __shared__ __align__(128) char dsm[];
    uint32_t sbase = smem_u32(dsm);
    __shared__ int toks[128];

    int tid  = threadIdx.x;
    int w    = tid >> 5;
    int lane = tid & 31;

    if (tid < 128) {
        int m = m0 + tid;
        toks[tid] = (m < cnt) ? g_pair_token[e * MAXT + m] : g_pair_token[e * MAXT];
    }
    __syncthreads();

    const __nv_bfloat16 *w1H, *w1L, *w3H, *w3L;
    if (e < NEXP) {
        size_t off = (size_t)e * HID * DIM;
        w1H = g_w1h + off; w1L = g_w1l + off;
        w3H = g_w3h + off; w3L = g_w3l + off;
    } else { w1H = g_sw1h; w1L = g_sw1l; w3H = g_sw3h; w3L = g_sw3l; }

    float acc[2][8][4];
    #pragma unroll
    for (int h = 0; h < 2; h++)
        #pragma unroll
        for (int j = 0; j < 8; j++)
            #pragma unroll
            for (int q = 0; q < 4; q++) acc[h][j][q] = 0.f;

    int lrow = tid >> 3, lcv = tid & 7;

    int mrow = (w >> 1) * 32;
    int ncl  = (w & 1) * 32;
    int aRow = (lane & 7) + ((lane >> 3) & 1) * 8;
    int aK   = (lane >> 4) * 8;
    int bRow = (lane & 7) + (lane >> 4) * 8;
    int bK   = ((lane >> 3) & 1) * 8;

    const int NC = DIM / 64;  // 16

    auto load_chunk = [&](int c) {
        int k0 = c * 64;
        uint32_t buf = sbase + (c % NSTAGE) * STAGE;
        #pragma unroll
        for (int i = 0; i < 4; i++) {
            int row = lrow + i * 32;
            const char* xh = (const char*)(g_xh + (size_t)toks[row] * DIM + k0);
            const char* xl = (const char*)(g_xl + (size_t)toks[row] * DIM + k0);
            cp16(buf + G1_AH + row * PITCH + lcv * 16, xh + lcv * 16);
            cp16(buf + G1_AL + row * PITCH + lcv * 16, xl + lcv * 16);
        }
        #pragma unroll
        for (int i = 0; i < 2; i++) {
            int row = lrow + i * 32;
            size_t wo = (size_t)(n0 + row) * DIM + k0;
            uint32_t so = row * PITCH + lcv * 16;
            cp16(buf + G1_B1H + so, (const char*)(w1H + wo) + lcv * 16);
            cp16(buf + G1_B3H + so, (const char*)(w3H + wo) + lcv * 16);
            cp16(buf + G1_B1L + so, (const char*)(w1L + wo) + lcv * 16);
            cp16(buf + G1_B3L + so, (const char*)(w3L + wo) + lcv * 16);
        }
        CP_COMMIT();
    };

    // register fragment double-buffers
    uint32_t fa[2][4][4];   // [buf][ah0, ah1, al0, al1]
    uint32_t fb[2][8][4];   // [buf][bh0..3, bl0..3]

    auto load_frags = [&](int P, int ks, uint32_t buf) {
        int kb = ks * 32;
        #pragma unroll
        for (int h = 0; h < 2; h++) {
            uint32_t ra = (mrow + h * 16 + aRow) * PITCH + kb + aK * 2;
            ldsm4(fa[P][h],     buf + G1_AH + ra);
            ldsm4(fa[P][2 + h], buf + G1_AL + ra);
        }
        #pragma unroll
        for (int g = 0; g < 4; g++) {
            uint32_t baseh = (g < 2) ? (buf + G1_B1H) : (buf + G1_B3H);
            uint32_t basel = (g < 2) ? (buf + G1_B1L) : (buf + G1_B3L);
            uint32_t ro = (ncl + (g & 1) * 16 + bRow) * PITCH + kb + bK * 2;
            ldsm4(fb[P][g],     baseh + ro);
            ldsm4(fb[P][4 + g], basel + ro);
        }
    };

    auto issue_mmas = [&](int P) {
        #pragma unroll
        for (int h = 0; h < 2; h++)
            #pragma unroll
            for (int j = 0; j < 8; j++) {
                mma16816(acc[h][j], fa[P][h],     &fb[P][j >> 1][(j & 1) * 2]);
                mma16816(acc[h][j], fa[P][2 + h], &fb[P][j >> 1][(j & 1) * 2]);
                mma16816(acc[h][j], fa[P][h],     &fb[P][4 + (j >> 1)][(j & 1) * 2]);
            }
    };

    load_chunk(0);
    load_chunk(1);

    for (int c = 0; c < NC; c++) {
        if (c + 1 < NC) CP_WAIT1();
        else            CP_WAIT0();
        __syncthreads();
        if (c + 2 < NC) load_chunk(c + 2);

        uint32_t buf = sbase + (c % NSTAGE) * STAGE;
        load_frags(0, 0, buf);
        #pragma unroll
        for (int ks = 0; ks < 4; ks++) {
            int P = ks & 1;
            if (ks < 3) load_frags(P ^ 1, ks + 1, buf);
            issue_mmas(P);
        }
    }

    // epilogue: silu(h1)*h3 -> act hi/lo bf16
    #pragma unroll
    for (int h = 0; h < 2; h++) {
        #pragma unroll
        for (int jj = 0; jj < 4; jj++) {
            int colb = n0 + ncl + jj * 8 + (lane & 3) * 2;
            float* a1 = acc[h][jj];
            float* a3 = acc[h][jj + 4];
            #pragma unroll
            for (int half = 0; half < 2; half++) {
                int r  = mrow + h * 16 + (lane >> 2) + half * 8;
                int gm = m0 + r;
                if (gm < cnt) {
                    float h1a = a1[half * 2],     h3a = a3[half * 2];
                    float h1b = a1[half * 2 + 1], h3b = a3[half * 2 + 1];
                    float v0 = h1a / (1.f + __expf(-h1a)) * h3a;
                    float v1 = h1b / (1.f + __expf(-h1b)) * h3b;
                    __nv_bfloat16 hh0 = __float2bfloat16(v0);
                    __nv_bfloat16 hh1 = __float2bfloat16(v1);
                    __nv_bfloat162 H; H.x = hh0; H.y = hh1;
                    size_t addr = ((size_t)e * MAXT + gm) * HID + colb;
                    *(__nv_bfloat162*)&g_acth[addr] = H;
                    __nv_bfloat162 L;
                    L.x = __float2bfloat16(v0 - __bfloat162float(hh0));
                    L.y = __float2bfloat16(v1 - __bfloat162float(hh1));
                    *(__nv_bfloat162*)&g_actl[addr] = L;
                }
            }
        }
    }
}

// ======================= GEMM2: out[tok] += w * (act @ W2^T) =======================
// CTA 128 pair rows x 128 dim cols, BK=64, 3-stage, 1 barrier/chunk,
// register-fragment double buffering, weighted atomicAdd epilogue.
__global__ __launch_bounds__(256, 1) void gemm2_mma(float* __restrict__ out) {
    int e   = blockIdx.z;
    int cnt = g_counts[e];
    int m0  = blockIdx.x * 128;
    if (m0 >= cnt) return;
    int n0  = blockIdx.y * 128;

    extern __shared__ __align__(128) char dsm[];
    uint32_t sbase = smem_u32(dsm);

    int tid  = threadIdx.x;
    int w    = tid >> 5;
    int lane = tid & 31;

    const __nv_bfloat16 *w2H, *w2L;
    if (e < NEXP) {
        size_t off = (size_t)e * DIM * HID;
        w2H = g_w2h + off; w2L = g_w2l + off;
    } else { w2H = g_sw2h; w2L = g_sw2l; }

    size_t rowbase = (size_t)e * MAXT + m0;

    float acc[2][8][4];
    #pragma unroll
    for (int h = 0; h < 2; h++)
        #pragma unroll
        for (int j = 0; j < 8; j++)
            #pragma unroll
            for (int q = 0; q < 4; q++) acc[h][j][q] = 0.f;

    int lrow = tid >> 3, lcv = tid & 7;

    int mrow = (w >> 1) * 32;
    int ncl  = (w & 1) * 64;
    int aRow = (lane & 7) + ((lane >> 3) & 1) * 8;
    int aK   = (lane >> 4) * 8;
    int bRow = (lane & 7) + (lane >> 4) * 8;
    int bK   = ((lane >> 3) & 1) * 8;

    const int NC = HID / 64;  // 8

    auto load_chunk = [&](int c) {
        int k0 = c * 64;
        uint32_t buf = sbase + (c % NSTAGE) * STAGE;
        #pragma unroll
        for (int i = 0; i < 4; i++) {
            int row = lrow + i * 32;
            uint32_t so = row * PITCH + lcv * 16;
            cp16(buf + G2_AH + so,
                 (const char*)(g_acth + (rowbase + row) * HID + k0) + lcv * 16);
            cp16(buf + G2_AL + so,
                 (const char*)(g_actl + (rowbase + row) * HID + k0) + lcv * 16);
            cp16(buf + G2_BH + so,
                 (const char*)(w2H + (size_t)(n0 + row) * HID + k0) + lcv * 16);
            cp16(buf + G2_BL + so,
                 (const char*)(w2L + (size_t)(n0 + row) * HID + k0) + lcv * 16);
        }
        CP_COMMIT();
    };

    uint32_t fa[2][4][4];
    uint32_t fb[2][8][4];

    auto load_frags = [&](int P, int ks, uint32_t buf) {
        int kb = ks * 32;
        #pragma unroll
        for (int h = 0; h < 2; h++) {
            uint32_t ra = (mrow + h * 16 + aRow) * PITCH + kb + aK * 2;
            ldsm4(fa[P][h],     buf + G2_AH + ra);
            ldsm4(fa[P][2 + h], buf + G2_AL + ra);
        }
        #pragma unroll
        for (int g = 0; g < 4; g++) {
            uint32_t ro = (ncl + g * 16 + bRow) * PITCH + kb + bK * 2;
            ldsm4(fb[P][g],     buf + G2_BH + ro);
            ldsm4(fb[P][4 + g], buf + G2_BL + ro);
        }
    };

    auto issue_mmas = [&](int P) {
        #pragma unroll
        for (int h = 0; h < 2; h++)
            #pragma unroll
            for (int j = 0; j < 8; j++) {
                mma16816(acc[h][j], fa[P][h],     &fb[P][j >> 1][(j & 1) * 2]);
                mma16816(acc[h][j], fa[P][2 + h], &fb[P][j >> 1][(j & 1) * 2]);
                mma16816(acc[h][j], fa[P][h],     &fb[P][4 + (j >> 1)][(j & 1) * 2]);
            }
    };

    load_chunk(0);
    load_chunk(1);

    for (int c = 0; c < NC; c++) {
        if (c + 1 < NC) CP_WAIT1();
        else            CP_WAIT0();
        __syncthreads();
        if (c + 2 < NC) load_chunk(c + 2);

        uint32_t buf = sbase + (c % NSTAGE) * STAGE;
        load_frags(0, 0, buf);
        #pragma unroll
        for (int ks = 0; ks < 4; ks++) {
            int P = ks & 1;
            if (ks < 3) load_frags(P ^ 1, ks + 1, buf);
            issue_mmas(P);
        }
    }

    // epilogue: weighted atomic accumulate into out
    #pragma unroll
    for (int h = 0; h < 2; h++) {
        #pragma unroll
        for (int half = 0; half < 2; half++) {
            int r  = mrow + h * 16 + (lane >> 2) + half * 8;
            int gm = m0 + r;
            if (gm < cnt) {
                int   tok = g_pair_token[e * MAXT + gm];
                float wgt = g_pair_weight[e * MAXT + gm];
                float* orow = out + (size_t)tok * DIM;
                #pragma unroll
                for (int j = 0; j < 8; j++) {
                    int col = n0 + ncl + j * 8 + (lane & 3) * 2;
                    atomicAdd(&orow[col],     acc[h][j][half * 2]     * wgt);
                    atomicAdd(&orow[col + 1], acc[h][j][half * 2 + 1] * wgt);
                }
            }
        }
    }
}

// ======================= launch =======================
extern "C" void kernel_launch(void* const* d_in, const int* in_sizes, int n_in,
                              void* d_out, int out_size) {
    const float* x    = (const float*)d_in[0];
    const float* gate = (const float*)d_in[1];
    const float* w1   = (const float*)d_in[2];
    const float* w3   = (const float*)d_in[3];
    const float* w2   = (const float*)d_in[4];
    const float* sw1  = (const float*)d_in[5];
    const float* sw3  = (const float*)d_in[6];
    const float* sw2  = (const float*)d_in[7];
    float* out = (float*)d_out;

    int T = in_sizes[0] / DIM;   // 2048

    cudaFuncSetAttribute(gemm1_mma, cudaFuncAttributeMaxDynamicSharedMemorySize, SMEM_DYN);
    cudaFuncSetAttribute(gemm2_mma, cudaFuncAttributeMaxDynamicSharedMemorySize, SMEM_DYN);

    // launch order (ncu captures kernel launch #3, 0-based):
    // 0:split_all 1:init 2:router 3:gemm1 4:gemm2
    const int NTOT = MAXT * DIM + 3 * (NEXP * HID * DIM) + 3 * (HID * DIM);
    split_all<<<(NTOT / 4 + 255) / 256, 256>>>(x, w1, w3, w2, sw1, sw3, sw2);

    init_kernel<<<(out_size / 4 + 255) / 256, 256>>>(out, out_size, T);
    router_kernel<<<T, 256>>>(x, gate, T);

    dim3 g1(MAXT / 128, HID / 64, NEXP1);
    gemm1_mma<<<g1, 256, SMEM_DYN>>>();

    dim3 g2(MAXT / 128, DIM / 128, NEXP1);
    gemm2_mma<<<g2, 256, SMEM_DYN>>>(out);
}

// round 16
// speedup vs baseline: 1.3777x; 1.3777x over previous
#include <cuda_runtime.h>
#include <cuda_bf16.h>
#include <cstdint>
#include <cstddef>

#define DIM 1024
#define HID 512
#define NEXP 16
#define TOPK 4
#define MAXT 2048
#define NEXP1 17

// ======================= device scratch (no allocs allowed) =======================
__device__ __nv_bfloat16 g_xh[MAXT * DIM], g_xl[MAXT * DIM];
__device__ __nv_bfloat16 g_w1h[NEXP * HID * DIM], g_w1l[NEXP * HID * DIM];
__device__ __nv_bfloat16 g_w3h[NEXP * HID * DIM], g_w3l[NEXP * HID * DIM];
__device__ __nv_bfloat16 g_w2h[NEXP * DIM * HID], g_w2l[NEXP * DIM * HID];
__device__ __nv_bfloat16 g_sw1h[HID * DIM], g_sw1l[HID * DIM];
__device__ __nv_bfloat16 g_sw3h[HID * DIM], g_sw3l[HID * DIM];
__device__ __nv_bfloat16 g_sw2h[DIM * HID], g_sw2l[DIM * HID];
__device__ __nv_bfloat16 g_acth[NEXP1 * MAXT * HID], g_actl[NEXP1 * MAXT * HID];
__device__ int   g_counts[NEXP1];
__device__ int   g_pair_token[NEXP1 * MAXT];
__device__ float g_pair_weight[NEXP1 * MAXT];

// ======================= helpers =======================
__device__ __forceinline__ uint32_t smem_u32(const void* p) {
    uint32_t a;
    asm("{ .reg .u64 t; cvta.to.shared.u64 t, %1; cvt.u32.u64 %0, t; }" : "=r"(a) : "l"(p));
    return a;
}
__device__ __forceinline__ void cp16(uint32_t s, const void* g) {
    asm volatile("cp.async.cg.shared.global [%0], [%1], 16;" :: "r"(s), "l"(g));
}
#define CP_COMMIT() asm volatile("cp.async.commit_group;" ::: "memory")
#define CP_WAIT1()  asm volatile("cp.async.wait_group 1;" ::: "memory")
#define CP_WAIT0()  asm volatile("cp.async.wait_group 0;" ::: "memory")

__device__ __forceinline__ void ldsm4(uint32_t* r, uint32_t addr) {
    asm volatile("ldmatrix.sync.aligned.m8n8.x4.shared.b16 {%0,%1,%2,%3}, [%4];"
                 : "=r"(r[0]), "=r"(r[1]), "=r"(r[2]), "=r"(r[3]) : "r"(addr));
}
__device__ __forceinline__ void mma16816(float* c, const uint32_t* a, const uint32_t* b) {
    asm volatile(
        "mma.sync.aligned.m16n8k16.row.col.f32.bf16.bf16.f32 "
        "{%0,%1,%2,%3}, {%4,%5,%6,%7}, {%8,%9}, {%0,%1,%2,%3};"
        : "+f"(c[0]), "+f"(c[1]), "+f"(c[2]), "+f"(c[3])
        : "r"(a[0]), "r"(a[1]), "r"(a[2]), "r"(a[3]), "r"(b[0]), "r"(b[1]));
}

// BK=64: 64 bf16 = 128B data + 16B pad = 144B pitch (conflict-free ldmatrix)
#define PITCH 144
#define AT_BYTES  (128 * PITCH)   // 18432
#define BT_BYTES  (64 * PITCH)    //  9216
// gemm1 stage: Ah Al | B1h B3h B1l B3l  = 73728
#define G1_AH 0
#define G1_AL AT_BYTES
#define G1_B1H (2 * AT_BYTES)
#define G1_B3H (2 * AT_BYTES + BT_BYTES)
#define G1_B1L (2 * AT_BYTES + 2 * BT_BYTES)
#define G1_B3L (2 * AT_BYTES + 3 * BT_BYTES)
// gemm2 stage: Ah Al Bh Bl (all 128-row) = 73728
#define G2_AH 0
#define G2_AL AT_BYTES
#define G2_BH (2 * AT_BYTES)
#define G2_BL (3 * AT_BYTES)
#define STAGE 73728
#define NSTAGE 3
#define SMEM_DYN (NSTAGE * STAGE)   // 221184

#define NTHREADS 512

// ======================= fused fp32 -> bf16 hi/lo split (ONE launch) =======================
__device__ __forceinline__ void split4(const float* __restrict__ src, int i,
                                       __nv_bfloat16* hi, __nv_bfloat16* lo) {
    float4 v = *(const float4*)(src + i);
    __nv_bfloat16 h0 = __float2bfloat16(v.x), h1 = __float2bfloat16(v.y);
    __nv_bfloat16 h2 = __float2bfloat16(v.z), h3 = __float2bfloat16(v.w);
    __nv_bfloat162 H0; H0.x = h0; H0.y = h1;
    __nv_bfloat162 H1; H1.x = h2; H1.y = h3;
    *(__nv_bfloat162*)(hi + i)     = H0;
    *(__nv_bfloat162*)(hi + i + 2) = H1;
    __nv_bfloat162 L0, L1;
    L0.x = __float2bfloat16(v.x - __bfloat162float(h0));
    L0.y = __float2bfloat16(v.y - __bfloat162float(h1));
    L1.x = __float2bfloat16(v.z - __bfloat162float(h2));
    L1.y = __float2bfloat16(v.w - __bfloat162float(h3));
    *(__nv_bfloat162*)(lo + i)     = L0;
    *(__nv_bfloat162*)(lo + i + 2) = L1;
}

__global__ void split_all(const float* __restrict__ x,
                          const float* __restrict__ w1, const float* __restrict__ w3,
                          const float* __restrict__ w2,
                          const float* __restrict__ sw1, const float* __restrict__ sw3,
                          const float* __restrict__ sw2) {
    const int NX = MAXT * DIM;
    const int NW = NEXP * HID * DIM;
    const int NS = HID * DIM;
    int i = (blockIdx.x * blockDim.x + threadIdx.x) * 4;
    if (i < NX) { split4(x,   i, g_xh,  g_xl);  return; }
    i -= NX;
    if (i < NW) { split4(w1,  i, g_w1h, g_w1l); return; }
    i -= NW;
    if (i < NW) { split4(w3,  i, g_w3h, g_w3l); return; }
    i -= NW;
    if (i < NW) { split4(w2,  i, g_w2h, g_w2l); return; }
    i -= NW;
    if (i < NS) { split4(sw1, i, g_sw1h, g_sw1l); return; }
    i -= NS;
    if (i < NS) { split4(sw3, i, g_sw3h, g_sw3l); return; }
    i -= NS;
    if (i < NS) { split4(sw2, i, g_sw2h, g_sw2l); }
}

// ======================= init: zero output + reset counters =======================
__global__ void init_kernel(float* __restrict__ out, int out_n, int T) {
    int i = (blockIdx.x * blockDim.x + threadIdx.x) * 4;
    if (i < out_n) *(float4*)(out + i) = make_float4(0.f, 0.f, 0.f, 0.f);
    if (blockIdx.x == 0) {
        int t = threadIdx.x;
        if (t < NEXP) g_counts[t] = 0;
        else if (t == NEXP) g_counts[NEXP] = T;
    }
}

// ======================= router =======================
__global__ void router_kernel(const float* __restrict__ x,
                              const float* __restrict__ gw, int T) {
    int t = blockIdx.x;
    __shared__ float xs[DIM];
    __shared__ float logits[NEXP];
    const float* xr = x + (size_t)t * DIM;
    for (int k = threadIdx.x; k < DIM; k += blockDim.x) xs[k] = xr[k];
    __syncthreads();

    int e = threadIdx.x >> 4;
    int l = threadIdx.x & 15;
    const float* w = gw + (size_t)e * DIM;
    float s = 0.f;
    for (int k = l; k < DIM; k += 16) s += xs[k] * w[k];
    for (int off = 8; off; off >>= 1) s += __shfl_down_sync(0xffffffffu, s, off, 16);
    if (l == 0) logits[e] = s;
    __syncthreads();

    if (threadIdx.x == 0) {
        float lv[NEXP];
        #pragma unroll
        for (int i = 0; i < NEXP; i++) lv[i] = logits[i];
        int   idx[TOPK];
        float val[TOPK];
        #pragma unroll
        for (int k = 0; k < TOPK; k++) {
            int bi = 0; float bv = -1e30f;
            #pragma unroll
            for (int i = 0; i < NEXP; i++) if (lv[i] > bv) { bv = lv[i]; bi = i; }
            idx[k] = bi; val[k] = bv; lv[bi] = -1e30f;
        }
        float m = val[0];
        float wv[TOPK], sum = 0.f;
        #pragma unroll
        for (int k = 0; k < TOPK; k++) { wv[k] = __expf(val[k] - m); sum += wv[k]; }
        float inv = 1.f / sum;
        #pragma unroll
        for (int k = 0; k < TOPK; k++) {
            int ee = idx[k];
            int slot = atomicAdd(&g_counts[ee], 1);
            g_pair_token[ee * MAXT + slot]  = t;
            g_pair_weight[ee * MAXT + slot] = wv[k] * inv;
        }
        g_pair_token[NEXP * MAXT + t]  = t;
        g_pair_weight[NEXP * MAXT + t] = 1.f;
    }
}

// ======================= GEMM1: act = silu(x@W1^T)*(x@W3^T) =======================
// CTA 128 tokens x 64 hid cols, BK=64, 3-stage cp.async, 1 barrier/chunk,
// 512 threads (16 warps, 4/SMSP): warp tile M16 x N32, flat r12-style inner loop.
__global__ __launch_bounds__(NTHREADS, 1) void gemm1_mma() {
    int e   = blockIdx.z;
    int cnt = g_counts[e];
    int m0  = blockIdx.x * 128;
    if (m0 >= cnt) return;
    int n0  = blockIdx.y * 64;

    extern __shared__ __align__(128) char dsm[];
    uint32_t sbase = smem_u32(dsm);
    __shared__ int toks[128];

    int tid  = threadIdx.x;
    int w    = tid >> 5;
    int lane = tid & 31;

    if (tid < 128) {
        int m = m0 + tid;
        toks[tid] = (m < cnt) ? g_pair_token[e * MAXT + m] : g_pair_token[e * MAXT];
    }
    __syncthreads();

    const __nv_bfloat16 *w1H, *w1L, *w3H, *w3L;
    if (e < NEXP) {
        size_t off = (size_t)e * HID * DIM;
        w1H = g_w1h + off; w1L = g_w1l + off;
        w3H = g_w3h + off; w3L = g_w3l + off;
    } else { w1H = g_sw1h; w1L = g_sw1l; w3H = g_sw3h; w3L = g_sw3l; }

    float acc[8][4];
    #pragma unroll
    for (int j = 0; j < 8; j++)
        #pragma unroll
        for (int q = 0; q < 4; q++) acc[j][q] = 0.f;

    // loaders (512 threads): A tiles 128 rows x 8 chunks -> 2 cp16/thread/tile
    int arow = tid >> 2, acv = (tid & 3) * 2;
    // B tiles 64 rows x 8 chunks -> 1 cp16/thread/tile
    int brow = tid >> 3, bcv = tid & 7;

    // warp tile: M16 at mrow, N32 (cols [ncl, ncl+32) of both W1 and W3)
    int mrow = (w >> 1) * 16;
    int ncl  = (w & 1) * 32;
    int aRow = (lane & 7) + ((lane >> 3) & 1) * 8;
    int aK   = (lane >> 4) * 8;
    int bRow = (lane & 7) + (lane >> 4) * 8;
    int bK   = ((lane >> 3) & 1) * 8;

    const int NC = DIM / 64;  // 16

    auto load_chunk = [&](int c) {
        int k0 = c * 64;
        uint32_t buf = sbase + (c % NSTAGE) * STAGE;
        {
            const char* xh = (const char*)(g_xh + (size_t)toks[arow] * DIM + k0);
            const char* xl = (const char*)(g_xl + (size_t)toks[arow] * DIM + k0);
            #pragma unroll
            for (int j = 0; j < 2; j++) {
                cp16(buf + G1_AH + arow * PITCH + (acv + j) * 16, xh + (acv + j) * 16);
                cp16(buf + G1_AL + arow * PITCH + (acv + j) * 16, xl + (acv + j) * 16);
            }
        }
        {
            size_t wo = (size_t)(n0 + brow) * DIM + k0;
            uint32_t so = brow * PITCH + bcv * 16;
            cp16(buf + G1_B1H + so, (const char*)(w1H + wo) + bcv * 16);
            cp16(buf + G1_B3H + so, (const char*)(w3H + wo) + bcv * 16);
            cp16(buf + G1_B1L + so, (const char*)(w1L + wo) + bcv * 16);
            cp16(buf + G1_B3L + so, (const char*)(w3L + wo) + bcv * 16);
        }
        CP_COMMIT();
    };

    load_chunk(0);
    load_chunk(1);

    for (int c = 0; c < NC; c++) {
        if (c + 1 < NC) CP_WAIT1();
        else            CP_WAIT0();
        __syncthreads();
        if (c + 2 < NC) load_chunk(c + 2);

        uint32_t buf = sbase + (c % NSTAGE) * STAGE;
        #pragma unroll
        for (int ks = 0; ks < 4; ks++) {
            int kb = ks * 32;
            uint32_t ah[4], al[4];
            {
                uint32_t ra = (mrow + aRow) * PITCH + kb + aK * 2;
                ldsm4(ah, buf + G1_AH + ra);
                ldsm4(al, buf + G1_AL + ra);
            }
            {   // hi B: ah*bh + al*bh
                uint32_t bh[4][4];
                #pragma unroll
                for (int g = 0; g < 4; g++) {
                    uint32_t base = (g < 2) ? (buf + G1_B1H) : (buf + G1_B3H);
                    int nloc = ncl + (g & 1) * 16;
                    ldsm4(bh[g], base + (nloc + bRow) * PITCH + kb + bK * 2);
                }
                #pragma unroll
                for (int j = 0; j < 8; j++) {
                    mma16816(acc[j], ah, &bh[j >> 1][(j & 1) * 2]);
                    mma16816(acc[j], al, &bh[j >> 1][(j & 1) * 2]);
                }
            }
            {   // lo B: ah*bl
                uint32_t bl[4][4];
                #pragma unroll
                for (int g = 0; g < 4; g++) {
                    uint32_t base = (g < 2) ? (buf + G1_B1L) : (buf + G1_B3L);
                    int nloc = ncl + (g & 1) * 16;
                    ldsm4(bl[g], base + (nloc + bRow) * PITCH + kb + bK * 2);
                }
                #pragma unroll
                for (int j = 0; j < 8; j++)
                    mma16816(acc[j], ah, &bl[j >> 1][(j & 1) * 2]);
            }
        }
    }

    // epilogue: silu(h1)*h3 -> act hi/lo bf16
    #pragma unroll
    for (int jj = 0; jj < 4; jj++) {
        int colb = n0 + ncl + jj * 8 + (lane & 3) * 2;
        float* a1 = acc[jj];
        float* a3 = acc[jj + 4];
        #pragma unroll
        for (int half = 0; half < 2; half++) {
            int r  = mrow + (lane >> 2) + half * 8;
            int gm = m0 + r;
            if (gm < cnt) {
                float h1a = a1[half * 2],     h3a = a3[half * 2];
                float h1b = a1[half * 2 + 1], h3b = a3[half * 2 + 1];
                float v0 = h1a / (1.f + __expf(-h1a)) * h3a;
                float v1 = h1b / (1.f + __expf(-h1b)) * h3b;
                __nv_bfloat16 hh0 = __float2bfloat16(v0);
                __nv_bfloat16 hh1 = __float2bfloat16(v1);
                __nv_bfloat162 H; H.x = hh0; H.y = hh1;
                size_t addr = ((size_t)e * MAXT + gm) * HID + colb;
                *(__nv_bfloat162*)&g_acth[addr] = H;
                __nv_bfloat162 L;
                L.x = __float2bfloat16(v0 - __bfloat162float(hh0));
                L.y = __float2bfloat16(v1 - __bfloat162float(hh1));
                *(__nv_bfloat162*)&g_actl[addr] = L;
            }
        }
    }
}

// ======================= GEMM2: out[tok] += w * (act @ W2^T) =======================
// CTA 128 pair rows x 128 dim cols, BK=64, 3-stage, 1 barrier/chunk,
// 512 threads: warp tile M16 x N64, weighted atomicAdd epilogue.
__global__ __launch_bounds__(NTHREADS, 1) void gemm2_mma(float* __restrict__ out) {
    int e   = blockIdx.z;
    int cnt = g_counts[e];
    int m0  = blockIdx.x * 128;
    if (m0 >= cnt) return;
    int n0  = blockIdx.y * 128;

    extern __shared__ __align__(128) char dsm[];
    uint32_t sbase = smem_u32(dsm);

    int tid  = threadIdx.x;
    int w    = tid >> 5;
    int lane = tid & 31;

    const __nv_bfloat16 *w2H, *w2L;
    if (e < NEXP) {
        size_t off = (size_t)e * DIM * HID;
        w2H = g_w2h + off; w2L = g_w2l + off;
    } else { w2H = g_sw2h; w2L = g_sw2l; }

    size_t rowbase = (size_t)e * MAXT + m0;

    float acc[8][4];
    #pragma unroll
    for (int j = 0; j < 8; j++)
        #pragma unroll
        for (int q = 0; q < 4; q++) acc[j][q] = 0.f;

    int arow = tid >> 2, acv = (tid & 3) * 2;

    int mrow = (w >> 1) * 16;
    int ncl  = (w & 1) * 64;
    int aRow = (lane & 7) + ((lane >> 3) & 1) * 8;
    int aK   = (lane >> 4) * 8;
    int bRow = (lane & 7) + (lane >> 4) * 8;
    int bK   = ((lane >> 3) & 1) * 8;

    const int NC = HID / 64;  // 8

    auto load_chunk = [&](int c) {
        int k0 = c * 64;
        uint32_t buf = sbase + (c % NSTAGE) * STAGE;
        uint32_t so = arow * PITCH;
        const char* ahp = (const char*)(g_acth + (rowbase + arow) * HID + k0);
        const char* alp = (const char*)(g_actl + (rowbase + arow) * HID + k0);
        const char* bhp = (const char*)(w2H + (size_t)(n0 + arow) * HID + k0);
        const char* blp = (const char*)(w2L + (size_t)(n0 + arow) * HID + k0);
        #pragma unroll
        for (int j = 0; j < 2; j++) {
            uint32_t o = so + (acv + j) * 16;
            cp16(buf + G2_AH + o, ahp + (acv + j) * 16);
            cp16(buf + G2_AL + o, alp + (acv + j) * 16);
            cp16(buf + G2_BH + o, bhp + (acv + j) * 16);
            cp16(buf + G2_BL + o, blp + (acv + j) * 16);
        }
        CP_COMMIT();
    };

    load_chunk(0);
    load_chunk(1);

    for (int c = 0; c < NC; c++) {
        if (c + 1 < NC) CP_WAIT1();
        else            CP_WAIT0();
        __syncthreads();
        if (c + 2 < NC) load_chunk(c + 2);

        uint32_t buf = sbase + (c % NSTAGE) * STAGE;
        #pragma unroll
        for (int ks = 0; ks < 4; ks++) {
            int kb = ks * 32;
            uint32_t ah[4], al[4];
            {
                uint32_t ra = (mrow + aRow) * PITCH + kb + aK * 2;
                ldsm4(ah, buf + G2_AH + ra);
                ldsm4(al, buf + G2_AL + ra);
            }
            {
                uint32_t bh[4][4];
                #pragma unroll
                for (int g = 0; g < 4; g++) {
                    int nloc = ncl + g * 16;
                    ldsm4(bh[g], buf + G2_BH + (nloc + bRow) * PITCH + kb + bK * 2);
                }
                #pragma unroll
                for (int j = 0; j < 8; j++) {
                    mma16816(acc[j], ah, &bh[j >> 1][(j & 1) * 2]);
                    mma16816(acc[j], al, &bh[j >> 1][(j & 1) * 2]);
                }
            }
            {
                uint32_t bl[4][4];
                #pragma unroll
                for (int g = 0; g < 4; g++) {
                    int nloc = ncl + g * 16;
                    ldsm4(bl[g], buf + G2_BL + (nloc + bRow) * PITCH + kb + bK * 2);
                }
                #pragma unroll
                for (int j = 0; j < 8; j++)
                    mma16816(acc[j], ah, &bl[j >> 1][(j & 1) * 2]);
            }
        }
    }

    // epilogue: weighted atomic accumulate into out
    #pragma unroll
    for (int half = 0; half < 2; half++) {
        int r  = mrow + (lane >> 2) + half * 8;
        int gm = m0 + r;
        if (gm < cnt) {
            int   tok = g_pair_token[e * MAXT + gm];
            float wgt = g_pair_weight[e * MAXT + gm];
            float* orow = out + (size_t)tok * DIM;
            #pragma unroll
            for (int j = 0; j < 8; j++) {
                int col = n0 + ncl + j * 8 + (lane & 3) * 2;
                atomicAdd(&orow[col],     acc[j][half * 2]     * wgt);
                atomicAdd(&orow[col + 1], acc[j][half * 2 + 1] * wgt);
            }
        }
    }
}

// ======================= launch =======================
extern "C" void kernel_launch(void* const* d_in, const int* in_sizes, int n_in,
                              void* d_out, int out_size) {
    const float* x    = (const float*)d_in[0];
    const float* gate = (const float*)d_in[1];
    const float* w1   = (const float*)d_in[2];
    const float* w3   = (const float*)d_in[3];
    const float* w2   = (const float*)d_in[4];
    const float* sw1  = (const float*)d_in[5];
    const float* sw3  = (const float*)d_in[6];
    const float* sw2  = (const float*)d_in[7];
    float* out = (float*)d_out;

    int T = in_sizes[0] / DIM;   // 2048

    cudaFuncSetAttribute(gemm1_mma, cudaFuncAttributeMaxDynamicSharedMemorySize, SMEM_DYN);
    cudaFuncSetAttribute(gemm2_mma, cudaFuncAttributeMaxDynamicSharedMemorySize, SMEM_DYN);

    // launch order (ncu captures kernel launch #3, 0-based):
    // 0:split_all 1:init 2:router 3:gemm1 4:gemm2
    const int NTOT = MAXT * DIM + 3 * (NEXP * HID * DIM) + 3 * (HID * DIM);
    split_all<<<(NTOT / 4 + 255) / 256, 256>>>(x, w1, w3, w2, sw1, sw3, sw2);

    init_kernel<<<(out_size / 4 + 255) / 256, 256>>>(out, out_size, T);
    router_kernel<<<T, 256>>>(x, gate, T);

    dim3 g1(MAXT / 128, HID / 64, NEXP1);
    gemm1_mma<<<g1, NTHREADS, SMEM_DYN>>>();

    dim3 g2(MAXT / 128, DIM / 128, NEXP1);
    gemm2_mma<<<g2, NTHREADS, SMEM_DYN>>>(out);
}

// round 17
// speedup vs baseline: 1.4974x; 1.0869x over previous
#include <cuda_runtime.h>
#include <cuda_bf16.h>
#include <cstdint>
#include <cstddef>

#define DIM 1024
#define HID 512
#define NEXP 16
#define TOPK 4
#define MAXT 2048
#define NEXP1 17

// ======================= device scratch (no allocs allowed) =======================
__device__ __nv_bfloat16 g_xh[MAXT * DIM], g_xl[MAXT * DIM];
__device__ __nv_bfloat16 g_w1h[NEXP * HID * DIM], g_w1l[NEXP * HID * DIM];
__device__ __nv_bfloat16 g_w3h[NEXP * HID * DIM], g_w3l[NEXP * HID * DIM];
__device__ __nv_bfloat16 g_w2h[NEXP * DIM * HID], g_w2l[NEXP * DIM * HID];
__device__ __nv_bfloat16 g_sw1h[HID * DIM], g_sw1l[HID * DIM];
__device__ __nv_bfloat16 g_sw3h[HID * DIM], g_sw3l[HID * DIM];
__device__ __nv_bfloat16 g_sw2h[DIM * HID], g_sw2l[DIM * HID];
__device__ __nv_bfloat16 g_acth[NEXP1 * MAXT * HID], g_actl[NEXP1 * MAXT * HID];
__device__ int   g_counts[NEXP1];
__device__ int   g_pair_token[NEXP1 * MAXT];
__device__ float g_pair_weight[NEXP1 * MAXT];

// ======================= helpers =======================
__device__ __forceinline__ uint32_t smem_u32(const void* p) {
    uint32_t a;
    asm("{ .reg .u64 t; cvta.to.shared.u64 t, %1; cvt.u32.u64 %0, t; }" : "=r"(a) : "l"(p));
    return a;
}
__device__ __forceinline__ void cp16(uint32_t s, const void* g) {
    asm volatile("cp.async.cg.shared.global [%0], [%1], 16;" :: "r"(s), "l"(g));
}
#define CP_COMMIT() asm volatile("cp.async.commit_group;" ::: "memory")
#define CP_WAIT1()  asm volatile("cp.async.wait_group 1;" ::: "memory")
#define CP_WAIT0()  asm volatile("cp.async.wait_group 0;" ::: "memory")

__device__ __forceinline__ void ldsm4(uint32_t* r, uint32_t addr) {
    asm volatile("ldmatrix.sync.aligned.m8n8.x4.shared.b16 {%0,%1,%2,%3}, [%4];"
                 : "=r"(r[0]), "=r"(r[1]), "=r"(r[2]), "=r"(r[3]) : "r"(addr));
}
__device__ __forceinline__ void mma16816(float* c, const uint32_t* a, const uint32_t* b) {
    asm volatile(
        "mma.sync.aligned.m16n8k16.row.col.f32.bf16.bf16.f32 "
        "{%0,%1,%2,%3}, {%4,%5,%6,%7}, {%8,%9}, {%0,%1,%2,%3};"
        : "+f"(c[0]), "+f"(c[1]), "+f"(c[2]), "+f"(c[3])
        : "r"(a[0]), "r"(a[1]), "r"(a[2]), "r"(a[3]), "r"(b[0]), "r"(b[1]));
}

// BK=64: 64 bf16 = 128B data + 16B pad = 144B pitch (conflict-free ldmatrix)
#define PITCH 144
#define AT_BYTES  (128 * PITCH)   // 18432
#define BT_BYTES  (64 * PITCH)    //  9216
// gemm1 stage: Ah Al | B1h B3h B1l B3l  = 73728
#define G1_AH 0
#define G1_AL AT_BYTES
#define G1_B1H (2 * AT_BYTES)
#define G1_B3H (2 * AT_BYTES + BT_BYTES)
#define G1_B1L (2 * AT_BYTES + 2 * BT_BYTES)
#define G1_B3L (2 * AT_BYTES + 3 * BT_BYTES)
// gemm2 stage: Ah Al Bh Bl (all 128-row) = 73728
#define G2_AH 0
#define G2_AL AT_BYTES
#define G2_BH (2 * AT_BYTES)
#define G2_BL (3 * AT_BYTES)
#define STAGE 73728
#define NSTAGE 3
#define SMEM_DYN (NSTAGE * STAGE)   // 221184

// ======================= fused fp32 -> bf16 hi/lo split (ONE launch) =======================
__device__ __forceinline__ void split4(const float* __restrict__ src, int i,
                                       __nv_bfloat16* hi, __nv_bfloat16* lo) {
    float4 v = *(const float4*)(src + i);
    __nv_bfloat16 h0 = __float2bfloat16(v.x), h1 = __float2bfloat16(v.y);
    __nv_bfloat16 h2 = __float2bfloat16(v.z), h3 = __float2bfloat16(v.w);
    __nv_bfloat162 H0; H0.x = h0; H0.y = h1;
    __nv_bfloat162 H1; H1.x = h2; H1.y = h3;
    *(__nv_bfloat162*)(hi + i)     = H0;
    *(__nv_bfloat162*)(hi + i + 2) = H1;
    __nv_bfloat162 L0, L1;
    L0.x = __float2bfloat16(v.x - __bfloat162float(h0));
    L0.y = __float2bfloat16(v.y - __bfloat162float(h1));
    L1.x = __float2bfloat16(v.z - __bfloat162float(h2));
    L1.y = __float2bfloat16(v.w - __bfloat162float(h3));
    *(__nv_bfloat162*)(lo + i)     = L0;
    *(__nv_bfloat162*)(lo + i + 2) = L1;
}

__global__ void split_all(const float* __restrict__ x,
                          const float* __restrict__ w1, const float* __restrict__ w3,
                          const float* __restrict__ w2,
                          const float* __restrict__ sw1, const float* __restrict__ sw3,
                          const float* __restrict__ sw2) {
    const int NX = MAXT * DIM;
    const int NW = NEXP * HID * DIM;
    const int NS = HID * DIM;
    int i = (blockIdx.x * blockDim.x + threadIdx.x) * 4;
    if (i < NX) { split4(x,   i, g_xh,  g_xl);  return; }
    i -= NX;
    if (i < NW) { split4(w1,  i, g_w1h, g_w1l); return; }
    i -= NW;
    if (i < NW) { split4(w3,  i, g_w3h, g_w3l); return; }
    i -= NW;
    if (i < NW) { split4(w2,  i, g_w2h, g_w2l); return; }
    i -= NW;
    if (i < NS) { split4(sw1, i, g_sw1h, g_sw1l); return; }
    i -= NS;
    if (i < NS) { split4(sw3, i, g_sw3h, g_sw3l); return; }
    i -= NS;
    if (i < NS) { split4(sw2, i, g_sw2h, g_sw2l); }
}

// ======================= init: zero output + reset counters =======================
__global__ void init_kernel(float* __restrict__ out, int out_n, int T) {
    int i = (blockIdx.x * blockDim.x + threadIdx.x) * 4;
    if (i < out_n) *(float4*)(out + i) = make_float4(0.f, 0.f, 0.f, 0.f);
    if (blockIdx.x == 0) {
        int t = threadIdx.x;
        if (t < NEXP) g_counts[t] = 0;
        else if (t == NEXP) g_counts[NEXP] = T;
    }
}

// ======================= router =======================
__global__ void router_kernel(const float* __restrict__ x,
                              const float* __restrict__ gw, int T) {
    int t = blockIdx.x;
    __shared__ float xs[DIM];
    __shared__ float logits[NEXP];
    const float* xr = x + (size_t)t * DIM;
    for (int k = threadIdx.x; k < DIM; k += blockDim.x) xs[k] = xr[k];
    __syncthreads();

    int e = threadIdx.x >> 4;
    int l = threadIdx.x & 15;
    const float* w = gw + (size_t)e * DIM;
    float s = 0.f;
    for (int k = l; k < DIM; k += 16) s += xs[k] * w[k];
    for (int off = 8; off; off >>= 1) s += __shfl_down_sync(0xffffffffu, s, off, 16);
    if (l == 0) logits[e] = s;
    __syncthreads();

    if (threadIdx.x == 0) {
        float lv[NEXP];
        #pragma unroll
        for (int i = 0; i < NEXP; i++) lv[i] = logits[i];
        int   idx[TOPK];
        float val[TOPK];
        #pragma unroll
        for (int k = 0; k < TOPK; k++) {
            int bi = 0; float bv = -1e30f;
            #pragma unroll
            for (int i = 0; i < NEXP; i++) if (lv[i] > bv) { bv = lv[i]; bi = i; }
            idx[k] = bi; val[k] = bv; lv[bi] = -1e30f;
        }
        float m = val[0];
        float wv[TOPK], sum = 0.f;
        #pragma unroll
        for (int k = 0; k < TOPK; k++) { wv[k] = __expf(val[k] - m); sum += wv[k]; }
        float inv = 1.f / sum;
        #pragma unroll
        for (int k = 0; k < TOPK; k++) {
            int ee = idx[k];
            int slot = atomicAdd(&g_counts[ee], 1);
            g_pair_token[ee * MAXT + slot]  = t;
            g_pair_weight[ee * MAXT + slot] = wv[k] * inv;
        }
        g_pair_token[NEXP * MAXT + t]  = t;
        g_pair_weight[NEXP * MAXT + t] = 1.f;
    }
}

// ======================= GEMM1: act = silu(x@W1^T)*(x@W3^T) =======================
// CTA 128 tokens x 64 hid cols, BK=64, 3-stage cp.async, 1 barrier/chunk.
// Per ks: load all frags, then THREE SEPARATE accumulator sweeps
// (ah*bh | al*bh | ah*bl) so dependent MMAs on one acc are 16 issues apart.
__global__ __launch_bounds__(256, 1) void gemm1_mma() {
    int e   = blockIdx.z;
    int cnt = g_counts[e];
    int m0  = blockIdx.x * 128;
    if (m0 >= cnt) return;
    int n0  = blockIdx.y * 64;

    extern __shared__ __align__(128) char dsm[];
    uint32_t sbase = smem_u32(dsm);
    __shared__ int toks[128];

    int tid  = threadIdx.x;
    int w    = tid >> 5;
    int lane = tid & 31;

    if (tid < 128) {
        int m = m0 + tid;
        toks[tid] = (m < cnt) ? g_pair_token[e * MAXT + m] : g_pair_token[e * MAXT];
    }
    __syncthreads();

    const __nv_bfloat16 *w1H, *w1L, *w3H, *w3L;
    if (e < NEXP) {
        size_t off = (size_t)e * HID * DIM;
        w1H = g_w1h + off; w1L = g_w1l + off;
        w3H = g_w3h + off; w3L = g_w3l + off;
    } else { w1H = g_sw1h; w1L = g_sw1l; w3H = g_sw3h; w3L = g_sw3l; }

    float acc[2][8][4];
    #pragma unroll
    for (int h = 0; h < 2; h++)
        #pragma unroll
        for (int j = 0; j < 8; j++)
            #pragma unroll
            for (int q = 0; q < 4; q++) acc[h][j][q] = 0.f;

    int lrow = tid >> 3, lcv = tid & 7;

    int mrow = (w >> 1) * 32;
    int ncl  = (w & 1) * 32;
    int aRow = (lane & 7) + ((lane >> 3) & 1) * 8;
    int aK   = (lane >> 4) * 8;
    int bRow = (lane & 7) + (lane >> 4) * 8;
    int bK   = ((lane >> 3) & 1) * 8;

    const int NC = DIM / 64;  // 16

    auto load_chunk = [&](int c) {
        int k0 = c * 64;
        uint32_t buf = sbase + (c % NSTAGE) * STAGE;
        #pragma unroll
        for (int i = 0; i < 4; i++) {
            int row = lrow + i * 32;
            const char* xh = (const char*)(g_xh + (size_t)toks[row] * DIM + k0);
            const char* xl = (const char*)(g_xl + (size_t)toks[row] * DIM + k0);
            cp16(buf + G1_AH + row * PITCH + lcv * 16, xh + lcv * 16);
            cp16(buf + G1_AL + row * PITCH + lcv * 16, xl + lcv * 16);
        }
        #pragma unroll
        for (int i = 0; i < 2; i++) {
            int row = lrow + i * 32;
            size_t wo = (size_t)(n0 + row) * DIM + k0;
            uint32_t so = row * PITCH + lcv * 16;
            cp16(buf + G1_B1H + so, (const char*)(w1H + wo) + lcv * 16);
            cp16(buf + G1_B3H + so, (const char*)(w3H + wo) + lcv * 16);
            cp16(buf + G1_B1L + so, (const char*)(w1L + wo) + lcv * 16);
            cp16(buf + G1_B3L + so, (const char*)(w3L + wo) + lcv * 16);
        }
        CP_COMMIT();
    };

    load_chunk(0);
    load_chunk(1);

    for (int c = 0; c < NC; c++) {
        if (c + 1 < NC) CP_WAIT1();
        else            CP_WAIT0();
        __syncthreads();
        if (c + 2 < NC) load_chunk(c + 2);

        uint32_t buf = sbase + (c % NSTAGE) * STAGE;
        #pragma unroll
        for (int ks = 0; ks < 4; ks++) {
            int kb = ks * 32;
            // load ALL fragments for this ks first
            uint32_t ah[2][4], al[2][4];
            #pragma unroll
            for (int h = 0; h < 2; h++) {
                uint32_t ra = (mrow + h * 16 + aRow) * PITCH + kb + aK * 2;
                ldsm4(ah[h], buf + G1_AH + ra);
                ldsm4(al[h], buf + G1_AL + ra);
            }
            uint32_t bh[4][4], bl[4][4];
            #pragma unroll
            for (int g = 0; g < 4; g++) {
                uint32_t baseh = (g < 2) ? (buf + G1_B1H) : (buf + G1_B3H);
                uint32_t basel = (g < 2) ? (buf + G1_B1L) : (buf + G1_B3L);
                uint32_t ro = (ncl + (g & 1) * 16 + bRow) * PITCH + kb + bK * 2;
                ldsm4(bh[g], baseh + ro);
                ldsm4(bl[g], basel + ro);
            }
            // sweep 1: ah*bh (16 independent MMAs)
            #pragma unroll
            for (int h = 0; h < 2; h++)
                #pragma unroll
                for (int j = 0; j < 8; j++)
                    mma16816(acc[h][j], ah[h], &bh[j >> 1][(j & 1) * 2]);
            // sweep 2: al*bh
            #pragma unroll
            for (int h = 0; h < 2; h++)
                #pragma unroll
                for (int j = 0; j < 8; j++)
                    mma16816(acc[h][j], al[h], &bh[j >> 1][(j & 1) * 2]);
            // sweep 3: ah*bl
            #pragma unroll
            for (int h = 0; h < 2; h++)
                #pragma unroll
                for (int j = 0; j < 8; j++)
                    mma16816(acc[h][j], ah[h], &bl[j >> 1][(j & 1) * 2]);
        }
    }

    // epilogue: silu(h1)*h3 -> act hi/lo bf16
    #pragma unroll
    for (int h = 0; h < 2; h++) {
        #pragma unroll
        for (int jj = 0; jj < 4; jj++) {
            int colb = n0 + ncl + jj * 8 + (lane & 3) * 2;
            float* a1 = acc[h][jj];
            float* a3 = acc[h][jj + 4];
            #pragma unroll
            for (int half = 0; half < 2; half++) {
                int r  = mrow + h * 16 + (lane >> 2) + half * 8;
                int gm = m0 + r;
                if (gm < cnt) {
                    float h1a = a1[half * 2],     h3a = a3[half * 2];
                    float h1b = a1[half * 2 + 1], h3b = a3[half * 2 + 1];
                    float v0 = h1a / (1.f + __expf(-h1a)) * h3a;
                    float v1 = h1b / (1.f + __expf(-h1b)) * h3b;
                    __nv_bfloat16 hh0 = __float2bfloat16(v0);
                    __nv_bfloat16 hh1 = __float2bfloat16(v1);
                    __nv_bfloat162 H; H.x = hh0; H.y = hh1;
                    size_t addr = ((size_t)e * MAXT + gm) * HID + colb;
                    *(__nv_bfloat162*)&g_acth[addr] = H;
                    __nv_bfloat162 L;
                    L.x = __float2bfloat16(v0 - __bfloat162float(hh0));
                    L.y = __float2bfloat16(v1 - __bfloat162float(hh1));
                    *(__nv_bfloat162*)&g_actl[addr] = L;
                }
            }
        }
    }
}

// ======================= GEMM2: out[tok] += w * (act @ W2^T) =======================
// CTA 128 pair rows x 128 dim cols, BK=64, 3-stage, 1 barrier/chunk,
// three separate accumulator sweeps, weighted atomicAdd epilogue.
__global__ __launch_bounds__(256, 1) void gemm2_mma(float* __restrict__ out) {
    int e   = blockIdx.z;
    int cnt = g_counts[e];
    int m0  = blockIdx.x * 128;
    if (m0 >= cnt) return;
    int n0  = blockIdx.y * 128;

    extern __shared__ __align__(128) char dsm[];
    uint32_t sbase = smem_u32(dsm);

    int tid  = threadIdx.x;
    int w    = tid >> 5;
    int lane = tid & 31;

    const __nv_bfloat16 *w2H, *w2L;
    if (e < NEXP) {
        size_t off = (size_t)e * DIM * HID;
        w2H = g_w2h + off; w2L = g_w2l + off;
    } else { w2H = g_sw2h; w2L = g_sw2l; }

    size_t rowbase = (size_t)e * MAXT + m0;

    float acc[2][8][4];
    #pragma unroll
    for (int h = 0; h < 2; h++)
        #pragma unroll
        for (int j = 0; j < 8; j++)
            #pragma unroll
            for (int q = 0; q < 4; q++) acc[h][j][q] = 0.f;

    int lrow = tid >> 3, lcv = tid & 7;

    int mrow = (w >> 1) * 32;
    int ncl  = (w & 1) * 64;
    int aRow = (lane & 7) + ((lane >> 3) & 1) * 8;
    int aK   = (lane >> 4) * 8;
    int bRow = (lane & 7) + (lane >> 4) * 8;
    int bK   = ((lane >> 3) & 1) * 8;

    const int NC = HID / 64;  // 8

    auto load_chunk = [&](int c) {
        int k0 = c * 64;
        uint32_t buf = sbase + (c % NSTAGE) * STAGE;
        #pragma unroll
        for (int i = 0; i < 4; i++) {
            int row = lrow + i * 32;
            uint32_t so = row * PITCH + lcv * 16;
            cp16(buf + G2_AH + so,
                 (const char*)(g_acth + (rowbase + row) * HID + k0) + lcv * 16);
            cp16(buf + G2_AL + so,
                 (const char*)(g_actl + (rowbase + row) * HID + k0) + lcv * 16);
            cp16(buf + G2_BH + so,
                 (const char*)(w2H + (size_t)(n0 + row) * HID + k0) + lcv * 16);
            cp16(buf + G2_BL + so,
                 (const char*)(w2L + (size_t)(n0 + row) * HID + k0) + lcv * 16);
        }
        CP_COMMIT();
    };

    load_chunk(0);
    load_chunk(1);

    for (int c = 0; c < NC; c++) {
        if (c + 1 < NC) CP_WAIT1();
        else            CP_WAIT0();
        __syncthreads();
        if (c + 2 < NC) load_chunk(c + 2);

        uint32_t buf = sbase + (c % NSTAGE) * STAGE;
        #pragma unroll
        for (int ks = 0; ks < 4; ks++) {
            int kb = ks * 32;
            uint32_t ah[2][4], al[2][4];
            #pragma unroll
            for (int h = 0; h < 2; h++) {
                uint32_t ra = (mrow + h * 16 + aRow) * PITCH + kb + aK * 2;
                ldsm4(ah[h], buf + G2_AH + ra);
                ldsm4(al[h], buf + G2_AL + ra);
            }
            uint32_t bh[4][4], bl[4][4];
            #pragma unroll
            for (int g = 0; g < 4; g++) {
                uint32_t ro = (ncl + g * 16 + bRow) * PITCH + kb + bK * 2;
                ldsm4(bh[g], buf + G2_BH + ro);
                ldsm4(bl[g], buf + G2_BL + ro);
            }
            #pragma unroll
            for (int h = 0; h < 2; h++)
                #pragma unroll
                for (int j = 0; j < 8; j++)
                    mma16816(acc[h][j], ah[h], &bh[j >> 1][(j & 1) * 2]);
            #pragma unroll
            for (int h = 0; h < 2; h++)
                #pragma unroll
                for (int j = 0; j < 8; j++)
                    mma16816(acc[h][j], al[h], &bh[j >> 1][(j & 1) * 2]);
            #pragma unroll
            for (int h = 0; h < 2; h++)
                #pragma unroll
                for (int j = 0; j < 8; j++)
                    mma16816(acc[h][j], ah[h], &bl[j >> 1][(j & 1) * 2]);
        }
    }

    // epilogue: weighted atomic accumulate into out
    #pragma unroll
    for (int h = 0; h < 2; h++) {
        #pragma unroll
        for (int half = 0; half < 2; half++) {
            int r  = mrow + h * 16 + (lane >> 2) + half * 8;
            int gm = m0 + r;
            if (gm < cnt) {
                int   tok = g_pair_token[e * MAXT + gm];
                float wgt = g_pair_weight[e * MAXT + gm];
                float* orow = out + (size_t)tok * DIM;
                #pragma unroll
                for (int j = 0; j < 8; j++) {
                    int col = n0 + ncl + j * 8 + (lane & 3) * 2;
                    atomicAdd(&orow[col],     acc[h][j][half * 2]     * wgt);
                    atomicAdd(&orow[col + 1], acc[h][j][half * 2 + 1] * wgt);
                }
            }
        }
    }
}

// ======================= launch =======================
extern "C" void kernel_launch(void* const* d_in, const int* in_sizes, int n_in,
                              void* d_out, int out_size) {
    const float* x    = (const float*)d_in[0];
    const float* gate = (const float*)d_in[1];
    const float* w1   = (const float*)d_in[2];
    const float* w3   = (const float*)d_in[3];
    const float* w2   = (const float*)d_in[4];
    const float* sw1  = (const float*)d_in[5];
    const float* sw3  = (const float*)d_in[6];
    const float* sw2  = (const float*)d_in[7];
    float* out = (float*)d_out;

    int T = in_sizes[0] / DIM;   // 2048

    cudaFuncSetAttribute(gemm1_mma, cudaFuncAttributeMaxDynamicSharedMemorySize, SMEM_DYN);
    cudaFuncSetAttribute(gemm2_mma, cudaFuncAttributeMaxDynamicSharedMemorySize, SMEM_DYN);

    // launch order (ncu captures kernel launch #3, 0-based):
    // 0:split_all 1:init 2:router 3:gemm1 4:gemm2
    const int NTOT = MAXT * DIM + 3 * (NEXP * HID * DIM) + 3 * (HID * DIM);
    split_all<<<(NTOT / 4 + 255) / 256, 256>>>(x, w1, w3, w2, sw1, sw3, sw2);

    init_kernel<<<(out_size / 4 + 255) / 256, 256>>>(out, out_size, T);
    router_kernel<<<T, 256>>>(x, gate, T);

    dim3 g1(MAXT / 128, HID / 64, NEXP1);
    gemm1_mma<<<g1, 256, SMEM_DYN>>>();

    dim3 g2(MAXT / 128, DIM / 128, NEXP1);
    gemm2_mma<<<g2, 256, SMEM_DYN>>>(out);
}